// round 17
// baseline (speedup 1.0000x reference)
#include <cuda_runtime.h>
#include <cuda_bf16.h>
#include <cuda_fp16.h>
#include <cstdint>
#define BB 4
#define SS 4096
#define DIN 512
#define DD 256
#define KST 264
#define PST 72
#define WST 72
#define TSZ 33792
#define SMP 202752
#define SMR 221184
#define SMT 224256
#define PBUF 92160
typedef __nv_bfloat162 bf2;
typedef uint32_t u32;

__device__ __half gQ[BB*SS*DD];
__device__ __half gK[2][BB*SS*DD];
__device__ __half gV[BB*SS*DD];
__device__ __nv_bfloat16 gWQ[2][DD*DIN], gWK[2][DD*DIN];
__device__ u32 gCtr;

__device__ __forceinline__ void sp2(float a, float b, bf2& h, bf2& l) {
 h.x = __float2bfloat16(a); h.y = __float2bfloat16(b);
 l.x = __float2bfloat16(a - __bfloat162float(h.x));
 l.y = __float2bfloat16(b - __bfloat162float(h.y));
}
__device__ __forceinline__ void sp2h(float a, float b, __half2& h, __half2& l) {
 __half ha = __float2half_rn(a), hb = __float2half_rn(b);
 h = __halves2half2(ha, hb);
 l = __halves2half2(__float2half_rn(a - __half2float(ha)),
                    __float2half_rn(b - __half2float(hb)));
}

__global__ void prep(const float* __restrict__ wq, const float* __restrict__ wk,
                     const float* __restrict__ v) {
 int bx = blockIdx.x, tid = threadIdx.x;
 if (bx < 512) {
  const float* in = bx < 256 ? wq : wk;
  __nv_bfloat16* oh = bx < 256 ? gWQ[0] : gWK[0];
  __nv_bfloat16* ol = bx < 256 ? gWQ[1] : gWK[1];
  int i = ((bx & 255)*256 + tid)*2;
  float2 x = *(const float2*)&in[i];
  bf2 h, l; sp2(x.x, x.y, h, l);
  *(bf2*)&oh[i] = h; *(bf2*)&ol[i] = l;
 } else {
  int i = ((bx - 512)*256 + tid)*4;
  float4 x = *(const float4*)&v[i];
  *(__half2*)&gV[i] = __floats2half2_rn(x.x, x.y);
  *(__half2*)&gV[i+2] = __floats2half2_rn(x.z, x.w);
 }
}

__device__ __forceinline__ void cpa(u32 dst, const void* src) {
 asm volatile("cp.async.ca.shared.global [%0], [%1], 16;" :: "r"(dst), "l"(src));
}
#define CPCOMMIT() asm volatile("cp.async.commit_group;" ::: "memory")
#define CPWAIT0() asm volatile("cp.async.wait_group 0;" ::: "memory")

__device__ __forceinline__ void lds(u32* r, u32 a) {
 asm volatile("ldmatrix.sync.aligned.m8n8.x4.shared.b16 {%0,%1,%2,%3},[%4];"
  : "=r"(r[0]), "=r"(r[1]), "=r"(r[2]), "=r"(r[3]) : "r"(a));
}
__device__ __forceinline__ void ldt(u32* r, u32 a) {
 asm volatile("ldmatrix.sync.aligned.m8n8.x4.trans.shared.b16 {%0,%1,%2,%3},[%4];"
  : "=r"(r[0]), "=r"(r[1]), "=r"(r[2]), "=r"(r[3]) : "r"(a));
}
__device__ __forceinline__ void mma(float* c, const u32* a, u32 b0, u32 b1) {
 asm volatile("mma.sync.aligned.m16n8k16.row.col.f32.bf16.bf16.f32 "
  "{%0,%1,%2,%3},{%4,%5,%6,%7},{%8,%9},{%0,%1,%2,%3};"
  : "+f"(c[0]), "+f"(c[1]), "+f"(c[2]), "+f"(c[3])
  : "r"(a[0]), "r"(a[1]), "r"(a[2]), "r"(a[3]), "r"(b0), "r"(b1));
}
__device__ __forceinline__ void mmah(float* c, const u32* a, u32 b0, u32 b1) {
 asm volatile("mma.sync.aligned.m16n8k16.row.col.f32.f16.f16.f32 "
  "{%0,%1,%2,%3},{%4,%5,%6,%7},{%8,%9},{%0,%1,%2,%3};"
  : "+f"(c[0]), "+f"(c[1]), "+f"(c[2]), "+f"(c[3])
  : "r"(a[0]), "r"(a[1]), "r"(a[2]), "r"(a[3]), "r"(b0), "r"(b1));
}
__device__ __forceinline__ void mma3(float* cA, float* cB, u32 (*A)[4], u32 (*B)[4]) {
 mma(cA, A[0], B[0][0], B[0][1]); mma(cB, A[0], B[0][2], B[0][3]);
 mma(cA, A[0], B[1][0], B[1][1]); mma(cB, A[0], B[1][2], B[1][3]);
 mma(cA, A[1], B[0][0], B[0][1]); mma(cB, A[1], B[0][2], B[0][3]);
}

__device__ __forceinline__ void stage_kv(u32 sb, int tid, int b, int kt, int vb) {
 for (int u = tid; u < 2048; u += 512) {
  int r = u >> 5, c = u & 31;
  size_t gi = (size_t)(b*SS + kt*64 + r)*DD + c*8;
  u32 so = (r*KST + c*8)*2;
  cpa(sb + 2*TSZ + so, gK[0] + gi);
  cpa(sb + 3*TSZ + so, gK[1] + gi);
  cpa(sb + (4+vb)*TSZ + so, gV + gi);
 }
 CPCOMMIT();
}

__global__ __launch_bounds__(512, 1)
void attn(const float* __restrict__ q, const float* __restrict__ key,
          const float* __restrict__ bq, const float* __restrict__ bk,
          const float* __restrict__ sfp, float* __restrict__ out)
{
 extern __shared__ char sm[];
 const u32 sb = (u32)__cvta_generic_to_shared(sm);
 const int tid = threadIdx.x, lane = tid & 31, wid = tid >> 5;

 // ===== phase 1: Q/K projections (4 tiles per CTA, 2 independent warp-groups)
 {
  const int g = wid >> 3, w8 = wid & 7, lt = tid & 255;
  const int pmb = w8 & 3, pnb = w8 >> 2, pt = lane & 3;
  char* ps = sm + g*PBUF;
  const u32 psb = sb + g*PBUF;
  const int plr = lane & 7, pqd = lane >> 3;
  const u32 paoff = ((pmb*16 + (lane&15))*WST + (lane>>4)*8)*2;
  const u32 pboff = ((pnb*128 + (pqd>>1)*8 + plr)*WST + (pqd&1)*8)*2;
  for (int it = 0; it < 2; it++) {
   const int tg = blockIdx.x*4 + it*2 + g;
   const int dst = tg >= 256, row0 = (tg & 255)*64;
   const float* X = dst ? key : q;
   const __nv_bfloat16* W0 = dst ? gWK[0] : gWQ[0];
   const __nv_bfloat16* W1 = dst ? gWK[1] : gWQ[1];
   const float* bias = dst ? bk : bq;
   float PO[16][4];
#pragma unroll
   for (int j = 0; j < 16; j++) PO[j][0] = PO[j][1] = PO[j][2] = PO[j][3] = 0.f;
   for (int kc = 0; kc < 8; kc++) {
#pragma unroll
    for (int u = lt; u < 1024; u += 256) {
     int r = u >> 4, c4 = (u & 15)*4;
     float4 x = *(const float4*)&X[(size_t)(row0+r)*DIN + kc*64 + c4];
     bf2 h0, l0, h1, l1;
     sp2(x.x, x.y, h0, l0); sp2(x.z, x.w, h1, l1);
     u32 so = (r*WST + c4)*2;
     *(bf2*)(ps + so) = h0; *(bf2*)(ps + so + 4) = h1;
     *(bf2*)(ps + 9216 + so) = l0; *(bf2*)(ps + 9216 + so + 4) = l1;
    }
#pragma unroll
    for (int u = lt; u < 2048; u += 256) {
     int r = u >> 3, c8 = u & 7;
     size_t gi = (size_t)r*DIN + kc*64 + c8*8;
     u32 so = (r*WST + c8*8)*2;
     *(uint4*)(ps + 18432 + so) = *(const uint4*)(W0 + gi);
     *(uint4*)(ps + 55296 + so) = *(const uint4*)(W1 + gi);
    }
    asm volatile("bar.sync %0, 256;" :: "r"(g+1) : "memory");
#pragma unroll
    for (int kk = 0; kk < 4; kk++) {
     u32 A[2][4];
     lds(A[0], psb + paoff + kk*32);
     lds(A[1], psb + 9216 + paoff + kk*32);
#pragma unroll
     for (int pr = 0; pr < 8; pr++) {
      u32 B[2][4];
      u32 of = pboff + pr*(16*WST*2) + kk*32;
      lds(B[0], psb + 18432 + of);
      lds(B[1], psb + 55296 + of);
      mma3(PO[2*pr], PO[2*pr+1], A, B);
     }
    }
    asm volatile("bar.sync %0, 256;" :: "r"(g+1) : "memory");
   }
   const int r0 = pmb*16 + (lane >> 2), r1 = r0 + 8;
#pragma unroll
   for (int j = 0; j < 16; j++) {
    int n0 = pnb*128 + j*8 + 2*pt;
    float2 bv = *(const float2*)&bias[n0];
    float a0 = PO[j][0] + bv.x, a1 = PO[j][1] + bv.y;
    float b0 = PO[j][2] + bv.x, b1 = PO[j][3] + bv.y;
    size_t oa = (size_t)(row0+r0)*DD + n0, ob = (size_t)(row0+r1)*DD + n0;
    if (dst == 0) {
     *(__half2*)&gQ[oa] = __floats2half2_rn(a0, a1);
     *(__half2*)&gQ[ob] = __floats2half2_rn(b0, b1);
    } else {
     __half2 h, l;
     sp2h(a0, a1, h, l);
     *(__half2*)&gK[0][oa] = h; *(__half2*)&gK[1][oa] = l;
     sp2h(b0, b1, h, l);
     *(__half2*)&gK[0][ob] = h; *(__half2*)&gK[1][ob] = l;
    }
   }
  }
 }
 // ===== device-wide barrier (all 128 CTAs resident at occ 1)
 __syncthreads();
 if (tid == 0) {
  __threadfence();
  atomicAdd(&gCtr, 1u);
  while (atomicAdd(&gCtr, 0u) < 128u) {}
  __threadfence();
 }
 __syncthreads();

 // ===== phase 2: attention (TQ=128, TK=64)
 float* sMx = (float*)(sm + SMR);
 float* sM = sMx + 256;
 float* sL = sMx + 512;
 const int mb = wid & 7, nb = wid >> 3, t = lane & 3;
 const int b = blockIdx.x >> 5, q0 = (blockIdx.x & 31)*128;
 const float sf = *sfp;

 stage_kv(sb, tid, b, 0, 0);
 for (int u = tid; u < 4096; u += 512) {
  int r = u >> 5, c = u & 31;
  *(uint4*)(sm + (r*KST + c*8)*2) =
   ((const uint4*)(gQ + (size_t)(b*SS + q0 + r)*DD))[c];
 }
 if (tid < 256) { sM[tid] = -1e30f; sL[tid] = 0.f; }

 const int lr = lane & 7, qd = lane >> 3;
 const u32 aoff = ((mb*16 + (lane&15))*KST + (lane>>4)*8)*2;
 const u32 koff = ((nb*32 + (qd>>1)*8 + lr)*KST + (qd&1)*8)*2;
 const u32 voff = (((qd&1)*8 + lr)*KST + nb*128 + (qd>>1)*8)*2;
 const u32 poff = ((mb*16 + (lane&15))*PST + (lane>>4)*8)*2;

 float O[16][4];
#pragma unroll
 for (int j = 0; j < 16; j++) O[j][0] = O[j][1] = O[j][2] = O[j][3] = 0.f;
 int rr[2]; rr[0] = mb*16 + (lane >> 2); rr[1] = rr[0] + 8;

 CPWAIT0();
 __syncthreads();

 for (int kt = 0; kt < SS/64; kt++) {
  const int vb = kt & 1;
  float Sv[4][4];
#pragma unroll
  for (int j = 0; j < 4; j++) Sv[j][0] = Sv[j][1] = Sv[j][2] = Sv[j][3] = 0.f;
#pragma unroll 4
  for (int kk = 0; kk < 16; kk++) {
   u32 A[4];
   lds(A, sb + aoff + kk*32);
#pragma unroll
   for (int n2 = 0; n2 < 2; n2++) {
    u32 B0[4], B1[4];
    u32 of = koff + n2*(16*KST*2) + kk*32;
    lds(B0, sb + 2*TSZ + of);
    lds(B1, sb + 3*TSZ + of);
    mmah(Sv[2*n2], A, B0[0], B0[1]); mmah(Sv[2*n2+1], A, B0[2], B0[3]);
    mmah(Sv[2*n2], A, B1[0], B1[1]); mmah(Sv[2*n2+1], A, B1[2], B1[3]);
   }
  }

  float mx[2] = {-1e30f, -1e30f};
#pragma unroll
  for (int j = 0; j < 4; j++) {
   Sv[j][0] *= sf; Sv[j][1] *= sf; Sv[j][2] *= sf; Sv[j][3] *= sf;
   mx[0] = fmaxf(mx[0], fmaxf(Sv[j][0], Sv[j][1]));
   mx[1] = fmaxf(mx[1], fmaxf(Sv[j][2], Sv[j][3]));
  }
#pragma unroll
  for (int h = 0; h < 2; h++) {
   mx[h] = fmaxf(mx[h], __shfl_xor_sync(~0u, mx[h], 1));
   mx[h] = fmaxf(mx[h], __shfl_xor_sync(~0u, mx[h], 2));
   if (t == 0) sMx[nb*128 + rr[h]] = mx[h];
  }
  __syncthreads();
  if (kt < SS/64 - 1) stage_kv(sb, tid, b, kt + 1, 1 - vb);

  const int par = kt & 1;
  float mn[2], sc[2], rs[2];
#pragma unroll
  for (int h = 0; h < 2; h++) {
   float mp = sM[par*128 + rr[h]];
   mn[h] = fmaxf(mp, fmaxf(sMx[rr[h]], sMx[128 + rr[h]]));
   sc[h] = __expf(mp - mn[h]);
   rs[h] = 0.f;
  }
#pragma unroll
  for (int j = 0; j < 4; j++) {
#pragma unroll
   for (int h = 0; h < 2; h++) {
    float pa = __expf(Sv[j][2*h] - mn[h]);
    float pb = __expf(Sv[j][2*h+1] - mn[h]);
    rs[h] += pa + pb;
    u32 po = (rr[h]*PST + nb*32 + j*8 + 2*t)*2;
    *(__half2*)(sm + SMP + po) = __floats2half2_rn(pa, pb);
   }
  }
#pragma unroll
  for (int h = 0; h < 2; h++) {
   rs[h] += __shfl_xor_sync(~0u, rs[h], 1);
   rs[h] += __shfl_xor_sync(~0u, rs[h], 2);
   if (t == 0) {
    sL[nb*128 + rr[h]] = sL[nb*128 + rr[h]]*sc[h] + rs[h];
    if (nb == 0) sM[(par^1)*128 + rr[h]] = mn[h];
   }
  }
#pragma unroll
  for (int j = 0; j < 16; j++) {
   O[j][0] *= sc[0]; O[j][1] *= sc[0]; O[j][2] *= sc[1]; O[j][3] *= sc[1];
  }
  __syncthreads();
#pragma unroll
  for (int ks = 0; ks < 4; ks++) {
   u32 P1[4];
   lds(P1, sb + SMP + poff + ks*32);
#pragma unroll
   for (int pr = 0; pr < 8; pr++) {
    u32 Vf[4];
    ldt(Vf, sb + (4+vb)*TSZ + voff + ks*(16*KST*2) + pr*32);
    mmah(O[2*pr], P1, Vf[0], Vf[1]);
    mmah(O[2*pr+1], P1, Vf[2], Vf[3]);
   }
  }
  CPWAIT0();
  __syncthreads();
 }

 float i0 = 1.f/(sL[rr[0]] + sL[128+rr[0]]);
 float i1 = 1.f/(sL[rr[1]] + sL[128+rr[1]]);
#pragma unroll
 for (int j = 0; j < 16; j++) {
  size_t oa = (size_t)(b*SS + q0 + rr[0])*DD + nb*128 + j*8 + 2*t;
  size_t ob = (size_t)(b*SS + q0 + rr[1])*DD + nb*128 + j*8 + 2*t;
  *(float2*)&out[oa] = make_float2(O[j][0]*i0, O[j][1]*i0);
  *(float2*)&out[ob] = make_float2(O[j][2]*i1, O[j][3]*i1);
 }
 if (tid == 0) atomicAdd(&gCtr, 0xFFFFFFFFu);
}

extern "C" void kernel_launch(void* const* d_in, const int* in_sizes, int n_in,
                              void* d_out, int out_size) {
 cudaFuncSetAttribute(attn, cudaFuncAttributeMaxDynamicSharedMemorySize, SMT);
 prep<<<4608, 256>>>((const float*)d_in[3], (const float*)d_in[5],
                     (const float*)d_in[2]);
 attn<<<BB*(SS/128), 512, SMT>>>((const float*)d_in[0], (const float*)d_in[1],
                                 (const float*)d_in[4], (const float*)d_in[6],
                                 (const float*)d_in[7], (float*)d_out);
}